// round 9
// baseline (speedup 1.0000x reference)
#include <cuda_runtime.h>
#include <cuda_fp16.h>
#include <cstdint>

// Problem dims (fixed per reference)
#define DIM_M 512
#define DIM_K 4096
#define DIM_N 11008

#define CTA_M 128
#define CTA_N 128
#define KSTEP 64                 // halves per K step
#define ITERS (DIM_K / KSTEP)    // 64
#define STAGES 3
#define GRID_MT (DIM_M / CTA_M)  // 4
#define GRID_NT (DIM_N / CTA_N)  // 86

// SMEM rows padded to 144B -> 8-row ldmatrix bases distinct mod 128 (conflict-free)
#define ROWB 144
#define A_TILE (128 * ROWB)                  // 18432
#define B_TILE (128 * ROWB)                  // 18432
#define STAGE_BYTES (A_TILE + B_TILE)        // 36864
#define SMEM_TOTAL (STAGES * STAGE_BYTES)    // 110592 (x2 CTAs = 221184 <= 228KB)

// x converted to fp16, row-major [512][4096]
__device__ __align__(16) __half g_x16[DIM_M * DIM_K];
// weights dequantized to fp16, row-major [11008][4096]
__device__ __align__(16) __half g_w16[(size_t)DIM_N * DIM_K];

__device__ __forceinline__ uint32_t smem_u32(const void* p) {
    uint32_t a;
    asm("{ .reg .u64 t; cvta.to.shared.u64 t, %1; cvt.u32.u64 %0, t; }" : "=r"(a) : "l"(p));
    return a;
}

__device__ __forceinline__ void cp_async16(uint32_t dst, const void* src) {
    asm volatile("cp.async.cg.shared.global [%0], [%1], 16;" :: "r"(dst), "l"(src));
}
__device__ __forceinline__ void cp_commit() { asm volatile("cp.async.commit_group;"); }

__device__ __forceinline__ void ldsm4(uint32_t* r, uint32_t addr) {
    asm volatile("ldmatrix.sync.aligned.m8n8.x4.shared.b16 {%0,%1,%2,%3}, [%4];"
                 : "=r"(r[0]), "=r"(r[1]), "=r"(r[2]), "=r"(r[3]) : "r"(addr));
}

__device__ __forceinline__ void mma16816(float* d, const uint32_t* a, const uint32_t* b) {
    asm volatile(
        "mma.sync.aligned.m16n8k16.row.col.f32.f16.f16.f32 "
        "{%0,%1,%2,%3}, {%4,%5,%6,%7}, {%8,%9}, {%0,%1,%2,%3};"
        : "+f"(d[0]), "+f"(d[1]), "+f"(d[2]), "+f"(d[3])
        : "r"(a[0]), "r"(a[1]), "r"(a[2]), "r"(a[3]), "r"(b[0]), "r"(b[1]));
}

__device__ __forceinline__ uint32_t pack2(float a, float b) {
    __half2 h = __floats2half2_rn(a, b);
    return *reinterpret_cast<uint32_t*>(&h);
}

// ---------------- kernel 0: x fp32 -> fp16 row-major ----------------
__global__ void __launch_bounds__(256) convert_x_kernel(const float* __restrict__ x) {
    int gid = blockIdx.x * blockDim.x + threadIdx.x;
    const float4* src = reinterpret_cast<const float4*>(x) + gid * 2;
    float4 f0 = __ldg(src);
    float4 f1 = __ldg(src + 1);
    uint4 v;
    v.x = pack2(f0.x, f0.y);
    v.y = pack2(f0.z, f0.w);
    v.z = pack2(f1.x, f1.y);
    v.w = pack2(f1.z, f1.w);
    reinterpret_cast<uint4*>(g_x16)[gid] = v;
}

// ---------------- kernel 1: dequant weights int32(4bit codes) -> fp16 ----------------
__global__ void __launch_bounds__(256) dequant_w_kernel(const int* __restrict__ w,
                                                        const float* __restrict__ saz) {
    int gid = blockIdx.x * blockDim.x + threadIdx.x;   // N*K/8 threads
    int n = gid >> 9;                // DIM_K/8 = 512 chunks per row
    int kc = (gid & 511) << 3;
    int g = kc >> 7;                 // group of 128
    float2 sz = __ldg(reinterpret_cast<const float2*>(saz) + (size_t)g * DIM_N + n);
    const float s = sz.x, z = sz.y;
    const int4* src = reinterpret_cast<const int4*>(w + (size_t)n * DIM_K + kc);
    int4 a = __ldg(src);
    int4 b = __ldg(src + 1);
    uint4 v;
    v.x = pack2((float)(a.x - 8) * s + z, (float)(a.y - 8) * s + z);
    v.y = pack2((float)(a.z - 8) * s + z, (float)(a.w - 8) * s + z);
    v.z = pack2((float)(b.x - 8) * s + z, (float)(b.y - 8) * s + z);
    v.w = pack2((float)(b.z - 8) * s + z, (float)(b.w - 8) * s + z);
    reinterpret_cast<uint4*>(g_w16)[gid] = v;
}

// ---------------- kernel 2: fp16 HMMA GEMM, warp tile 64x64, 4 warps ----------------
__global__ void __launch_bounds__(128, 2) gemm_kernel(float* __restrict__ out) {
    extern __shared__ __align__(1024) char smem[];
    const uint32_t sb = smem_u32(smem);
    const int tid = threadIdx.x;
    const int wid = tid >> 5;
    const int lid = tid & 31;

    // m-fast grid ordering: 4 CTAs sharing a weight N-tile run concurrently -> L2 reuse
    const int mtile = blockIdx.x & 3;
    const int ntile = blockIdx.x >> 2;
    const int mbase = mtile * CTA_M;
    const int nbase = ntile * CTA_N;

    // 2x2 warp grid, warp tile 64x64
    const int m0w = (wid & 1) * 64;
    const int n0w = (wid >> 1) * 64;

    // ---- loaders: each tile 128 rows x 8 chunks(16B) = 1024 chunks; 8 chunks/thread ----
    const int r0 = tid >> 3;         // 0..15
    const int c  = tid & 7;          // 0..7
    const __half* aG = g_x16 + (size_t)(mbase + r0) * DIM_K + c * 8;
    const __half* bG = g_w16 + (size_t)(nbase + r0) * DIM_K + c * 8;
    const uint32_t ld_off = (uint32_t)r0 * ROWB + c * 16;
    const size_t gstep16 = (size_t)16 * DIM_K;
    const uint32_t sstep16 = 16u * ROWB;

    // ---- ldmatrix lane bases ----
    const uint32_t a_lane_off = (uint32_t)(m0w + (lid & 15)) * ROWB + ((lid >> 4) << 4);
    const uint32_t b_lane_off = (uint32_t)(n0w + (lid & 7) + ((lid >> 4) & 1) * 8) * ROWB
                                + (((lid >> 3) & 1) << 4);

    float d[4][8][4];
    #pragma unroll
    for (int i = 0; i < 4; ++i)
        #pragma unroll
        for (int j = 0; j < 8; ++j)
            #pragma unroll
            for (int k = 0; k < 4; ++k) d[i][j][k] = 0.f;

    #define ISSUE_STAGE(ks, buf) do {                                     \
        const uint32_t stA = sb + (buf) * STAGE_BYTES + ld_off;           \
        const __half* sa = aG + (ks) * KSTEP;                             \
        const uint32_t stB = stA + A_TILE;                                \
        const __half* sbp = bG + (ks) * KSTEP;                            \
        _Pragma("unroll")                                                 \
        for (int j = 0; j < 8; ++j) {                                     \
            cp_async16(stA + j * sstep16, sa + j * gstep16);              \
            cp_async16(stB + j * sstep16, sbp + j * gstep16);             \
        }                                                                 \
    } while (0)

    // ---- prologue: stages 0..1 in flight ----
    #pragma unroll
    for (int s = 0; s < STAGES - 1; ++s) { ISSUE_STAGE(s, s); cp_commit(); }

    int buf = 0;
    for (int ks = 0; ks < ITERS; ++ks) {
        asm volatile("cp.async.wait_group %0;" :: "n"(STAGES - 2));
        __syncthreads();

        // issue into the buffer consumed at iteration ks-1 (sync above certified it free)
        const int pf = ks + STAGES - 1;
        if (pf < ITERS) {
            const int pbuf = (buf + STAGES - 1) % STAGES;
            ISSUE_STAGE(pf, pbuf);
        }
        cp_commit();

        const uint32_t aBase = sb + buf * STAGE_BYTES + a_lane_off;
        const uint32_t bBase = sb + buf * STAGE_BYTES + A_TILE + b_lane_off;
        #pragma unroll
        for (int kc = 0; kc < 4; ++kc) {
            uint32_t a[4][4], b[8][2];
            #pragma unroll
            for (int mt = 0; mt < 4; ++mt)
                ldsm4(a[mt], aBase + (uint32_t)mt * (16 * ROWB) + kc * 32);
            #pragma unroll
            for (int nt = 0; nt < 4; ++nt) {
                uint32_t t[4];
                ldsm4(t, bBase + (uint32_t)nt * (16 * ROWB) + kc * 32);
                b[2 * nt][0] = t[0]; b[2 * nt][1] = t[1];
                b[2 * nt + 1][0] = t[2]; b[2 * nt + 1][1] = t[3];
            }
            #pragma unroll
            for (int mt = 0; mt < 4; ++mt)
                #pragma unroll
                for (int n8 = 0; n8 < 8; ++n8)
                    mma16816(d[mt][n8], a[mt], b[n8]);
        }

        if (++buf == STAGES) buf = 0;
    }

    // ---- epilogue: registers -> gmem fp32 ----
    const int g = lid >> 2;
    const int tc = (lid & 3) * 2;
    #pragma unroll
    for (int mt = 0; mt < 4; ++mt) {
        const int row0 = mbase + m0w + mt * 16 + g;
        #pragma unroll
        for (int n8 = 0; n8 < 8; ++n8) {
            const int col = nbase + n0w + n8 * 8 + tc;
            float2 lo, hi;
            lo.x = d[mt][n8][0]; lo.y = d[mt][n8][1];
            hi.x = d[mt][n8][2]; hi.y = d[mt][n8][3];
            *reinterpret_cast<float2*>(out + (size_t)row0 * DIM_N + col) = lo;
            *reinterpret_cast<float2*>(out + (size_t)(row0 + 8) * DIM_N + col) = hi;
        }
    }
}

extern "C" void kernel_launch(void* const* d_in, const int* in_sizes, int n_in,
                              void* d_out, int out_size) {
    const float* x   = (const float*)d_in[0];
    const int*   w   = (const int*)d_in[1];
    const float* saz = (const float*)d_in[2];
    float* out = (float*)d_out;

    cudaFuncSetAttribute(gemm_kernel, cudaFuncAttributeMaxDynamicSharedMemorySize, SMEM_TOTAL);

    convert_x_kernel<<<(DIM_M * DIM_K / 8) / 256, 256>>>(x);
    dequant_w_kernel<<<((size_t)DIM_N * DIM_K / 8) / 256, 256>>>(w, saz);
    gemm_kernel<<<GRID_MT * GRID_NT, 128, SMEM_TOTAL>>>(out);
}

// round 11
// speedup vs baseline: 1.1271x; 1.1271x over previous
#include <cuda_runtime.h>
#include <cuda_fp16.h>
#include <cstdint>

// Problem dims (fixed per reference)
#define DIM_M 512
#define DIM_K 4096
#define DIM_N 11008

#define CTA_M 128
#define CTA_N 128
#define KSTEP 64                 // halves per K step
#define SPLITK 4
#define K_PER (DIM_K / SPLITK)   // 1024
#define ITERS (K_PER / KSTEP)    // 16
#define STAGES 3
#define GRID_MT (DIM_M / CTA_M)  // 4
#define GRID_NT (DIM_N / CTA_N)  // 86

// SMEM rows padded to 144B -> 8-row ldmatrix bases distinct mod 128 (conflict-free)
#define ROWB 144
#define A_TILE (128 * ROWB)                  // 18432
#define B_TILE (128 * ROWB)                  // 18432
#define STAGE_BYTES (A_TILE + B_TILE)        // 36864
#define SMEM_TOTAL (STAGES * STAGE_BYTES)    // 110592 (x2 CTAs = 221184 <= 228KB)

// x converted to fp16, row-major [512][4096]
__device__ __align__(16) __half g_x16[DIM_M * DIM_K];
// weights dequantized to fp16, row-major [11008][4096]
__device__ __align__(16) __half g_w16[(size_t)DIM_N * DIM_K];
// split-K fp32 partials [SPLITK][512][11008]
__device__ __align__(16) float g_partial[(size_t)SPLITK * DIM_M * DIM_N];

__device__ __forceinline__ uint32_t smem_u32(const void* p) {
    uint32_t a;
    asm("{ .reg .u64 t; cvta.to.shared.u64 t, %1; cvt.u32.u64 %0, t; }" : "=r"(a) : "l"(p));
    return a;
}

__device__ __forceinline__ void cp_async16(uint32_t dst, const void* src) {
    asm volatile("cp.async.cg.shared.global [%0], [%1], 16;" :: "r"(dst), "l"(src));
}
__device__ __forceinline__ void cp_commit() { asm volatile("cp.async.commit_group;"); }

__device__ __forceinline__ void ldsm4(uint32_t* r, uint32_t addr) {
    asm volatile("ldmatrix.sync.aligned.m8n8.x4.shared.b16 {%0,%1,%2,%3}, [%4];"
                 : "=r"(r[0]), "=r"(r[1]), "=r"(r[2]), "=r"(r[3]) : "r"(addr));
}

__device__ __forceinline__ void mma16816(float* d, const uint32_t* a, const uint32_t* b) {
    asm volatile(
        "mma.sync.aligned.m16n8k16.row.col.f32.f16.f16.f32 "
        "{%0,%1,%2,%3}, {%4,%5,%6,%7}, {%8,%9}, {%0,%1,%2,%3};"
        : "+f"(d[0]), "+f"(d[1]), "+f"(d[2]), "+f"(d[3])
        : "r"(a[0]), "r"(a[1]), "r"(a[2]), "r"(a[3]), "r"(b[0]), "r"(b[1]));
}

__device__ __forceinline__ uint32_t pack2(float a, float b) {
    __half2 h = __floats2half2_rn(a, b);
    return *reinterpret_cast<uint32_t*>(&h);
}

// ---------------- kernel 0: x fp32 -> fp16 row-major ----------------
__global__ void __launch_bounds__(256) convert_x_kernel(const float* __restrict__ x) {
    int gid = blockIdx.x * blockDim.x + threadIdx.x;
    const float4* src = reinterpret_cast<const float4*>(x) + gid * 2;
    float4 f0 = __ldg(src);
    float4 f1 = __ldg(src + 1);
    uint4 v;
    v.x = pack2(f0.x, f0.y);
    v.y = pack2(f0.z, f0.w);
    v.z = pack2(f1.x, f1.y);
    v.w = pack2(f1.z, f1.w);
    reinterpret_cast<uint4*>(g_x16)[gid] = v;
}

// ---------------- kernel 1: dequant weights int32(4bit codes) -> fp16 ----------------
__global__ void __launch_bounds__(256) dequant_w_kernel(const int* __restrict__ w,
                                                        const float* __restrict__ saz) {
    int gid = blockIdx.x * blockDim.x + threadIdx.x;   // N*K/8 threads
    int n = gid >> 9;                // DIM_K/8 = 512 chunks per row
    int kc = (gid & 511) << 3;
    int g = kc >> 7;                 // group of 128
    float2 sz = __ldg(reinterpret_cast<const float2*>(saz) + (size_t)g * DIM_N + n);
    const float s = sz.x, z = sz.y;
    const int4* src = reinterpret_cast<const int4*>(w + (size_t)n * DIM_K + kc);
    int4 a = __ldg(src);
    int4 b = __ldg(src + 1);
    uint4 v;
    v.x = pack2((float)(a.x - 8) * s + z, (float)(a.y - 8) * s + z);
    v.y = pack2((float)(a.z - 8) * s + z, (float)(a.w - 8) * s + z);
    v.z = pack2((float)(b.x - 8) * s + z, (float)(b.y - 8) * s + z);
    v.w = pack2((float)(b.z - 8) * s + z, (float)(b.w - 8) * s + z);
    reinterpret_cast<uint4*>(g_w16)[gid] = v;
}

// ---------------- kernel 2: fp16 HMMA GEMM, split-K x4, warp tile 64x32 ----------------
__global__ void __launch_bounds__(256, 2) gemm_kernel() {
    extern __shared__ __align__(1024) char smem[];
    const uint32_t sb = smem_u32(smem);
    const int tid = threadIdx.x;
    const int wid = tid >> 5;
    const int lid = tid & 31;

    // decode: mtile fastest (4), then kq (4), then ntile -> 16 adjacent CTAs share a B slab
    const int mtile = blockIdx.x & 3;
    const int kq = (blockIdx.x >> 2) & 3;
    const int ntile = blockIdx.x >> 4;
    const int mbase = mtile * CTA_M;
    const int nbase = ntile * CTA_N;
    const int kbase = kq * K_PER;

    // 2x4 warp grid, warp tile 64x32 (4 m16 sub-tiles per warp)
    const int m0w = (wid & 1) * 64;
    const int n0w = (wid >> 1) * 32;

    // ---- loaders: each tile 128 rows x 8 chunks(16B) = 1024 chunks; 4 chunks/thread ----
    const int r0 = tid >> 3;         // 0..31
    const int c  = tid & 7;          // 0..7
    const __half* aG = g_x16 + (size_t)(mbase + r0) * DIM_K + kbase + c * 8;
    const __half* bG = g_w16 + (size_t)(nbase + r0) * DIM_K + kbase + c * 8;
    const uint32_t ld_off = (uint32_t)r0 * ROWB + c * 16;
    const size_t gstep32 = (size_t)32 * DIM_K;
    const uint32_t sstep32 = 32u * ROWB;

    // ---- ldmatrix lane bases ----
    const uint32_t a_lane_off = (uint32_t)(m0w + (lid & 15)) * ROWB + ((lid >> 4) << 4);
    const uint32_t b_lane_off = (uint32_t)(n0w + (lid & 7) + ((lid >> 4) & 1) * 8) * ROWB
                                + (((lid >> 3) & 1) << 4);

    float d[4][4][4];
    #pragma unroll
    for (int i = 0; i < 4; ++i)
        #pragma unroll
        for (int j = 0; j < 4; ++j)
            #pragma unroll
            for (int k = 0; k < 4; ++k) d[i][j][k] = 0.f;

    #define ISSUE_STAGE(ks, buf) do {                                     \
        const uint32_t stA = sb + (buf) * STAGE_BYTES + ld_off;           \
        const __half* sa = aG + (ks) * KSTEP;                             \
        cp_async16(stA,               sa);                                \
        cp_async16(stA + sstep32,     sa + gstep32);                      \
        cp_async16(stA + 2 * sstep32, sa + 2 * gstep32);                  \
        cp_async16(stA + 3 * sstep32, sa + 3 * gstep32);                  \
        const uint32_t stB = stA + A_TILE;                                \
        const __half* sbp = bG + (ks) * KSTEP;                            \
        cp_async16(stB,               sbp);                               \
        cp_async16(stB + sstep32,     sbp + gstep32);                     \
        cp_async16(stB + 2 * sstep32, sbp + 2 * gstep32);                 \
        cp_async16(stB + 3 * sstep32, sbp + 3 * gstep32);                 \
    } while (0)

    // ---- prologue: stages 0..1 in flight ----
    #pragma unroll
    for (int s = 0; s < STAGES - 1; ++s) { ISSUE_STAGE(s, s); cp_commit(); }

    int buf = 0;
    for (int ks = 0; ks < ITERS; ++ks) {
        asm volatile("cp.async.wait_group %0;" :: "n"(STAGES - 2));
        __syncthreads();

        // issue into the buffer consumed at iteration ks-1 (sync above certified it free)
        const int pf = ks + STAGES - 1;
        if (pf < ITERS) {
            const int pbuf = (buf + STAGES - 1) % STAGES;
            ISSUE_STAGE(pf, pbuf);
        }
        cp_commit();

        const uint32_t aBase = sb + buf * STAGE_BYTES + a_lane_off;
        const uint32_t bBase = sb + buf * STAGE_BYTES + A_TILE + b_lane_off;
        #pragma unroll
        for (int kc = 0; kc < 4; ++kc) {
            uint32_t a[4][4], b[4][2];
            #pragma unroll
            for (int mt = 0; mt < 4; ++mt)
                ldsm4(a[mt], aBase + (uint32_t)mt * (16 * ROWB) + kc * 32);
            #pragma unroll
            for (int nt = 0; nt < 2; ++nt) {
                uint32_t t[4];
                ldsm4(t, bBase + (uint32_t)nt * (16 * ROWB) + kc * 32);
                b[2 * nt][0] = t[0]; b[2 * nt][1] = t[1];
                b[2 * nt + 1][0] = t[2]; b[2 * nt + 1][1] = t[3];
            }
            #pragma unroll
            for (int mt = 0; mt < 4; ++mt)
                #pragma unroll
                for (int n8 = 0; n8 < 4; ++n8)
                    mma16816(d[mt][n8], a[mt], b[n8]);
        }

        if (++buf == STAGES) buf = 0;
    }

    // ---- epilogue: registers -> fp32 split-K partial ----
    float* pout = g_partial + (size_t)kq * DIM_M * DIM_N;
    const int g = lid >> 2;
    const int tc = (lid & 3) * 2;
    #pragma unroll
    for (int mt = 0; mt < 4; ++mt) {
        const int row0 = mbase + m0w + mt * 16 + g;
        #pragma unroll
        for (int n8 = 0; n8 < 4; ++n8) {
            const int col = nbase + n0w + n8 * 8 + tc;
            float2 lo, hi;
            lo.x = d[mt][n8][0]; lo.y = d[mt][n8][1];
            hi.x = d[mt][n8][2]; hi.y = d[mt][n8][3];
            *reinterpret_cast<float2*>(pout + (size_t)row0 * DIM_N + col) = lo;
            *reinterpret_cast<float2*>(pout + (size_t)(row0 + 8) * DIM_N + col) = hi;
        }
    }
}

// ---------------- kernel 3: sum split-K partials -> out ----------------
__global__ void __launch_bounds__(256) reduce_kernel(float* __restrict__ out) {
    const size_t gid = (size_t)blockIdx.x * blockDim.x + threadIdx.x;  // per float4
    const float4* p = reinterpret_cast<const float4*>(g_partial);
    const size_t q = (size_t)DIM_M * DIM_N / 4;
    float4 a = p[gid];
    float4 b = p[gid + q];
    float4 c = p[gid + 2 * q];
    float4 e = p[gid + 3 * q];
    float4 r;
    r.x = (a.x + b.x) + (c.x + e.x);
    r.y = (a.y + b.y) + (c.y + e.y);
    r.z = (a.z + b.z) + (c.z + e.z);
    r.w = (a.w + b.w) + (c.w + e.w);
    reinterpret_cast<float4*>(out)[gid] = r;
}

extern "C" void kernel_launch(void* const* d_in, const int* in_sizes, int n_in,
                              void* d_out, int out_size) {
    const float* x   = (const float*)d_in[0];
    const int*   w   = (const int*)d_in[1];
    const float* saz = (const float*)d_in[2];
    float* out = (float*)d_out;

    cudaFuncSetAttribute(gemm_kernel, cudaFuncAttributeMaxDynamicSharedMemorySize, SMEM_TOTAL);

    convert_x_kernel<<<(DIM_M * DIM_K / 8) / 256, 256>>>(x);
    dequant_w_kernel<<<((size_t)DIM_N * DIM_K / 8) / 256, 256>>>(w, saz);
    gemm_kernel<<<GRID_MT * GRID_NT * SPLITK, 256, SMEM_TOTAL>>>();
    reduce_kernel<<<(DIM_M * DIM_N / 4) / 256, 256>>>(out);
}

// round 12
// speedup vs baseline: 1.1599x; 1.0291x over previous
#include <cuda_runtime.h>
#include <cuda_fp16.h>
#include <cstdint>

// Problem dims (fixed per reference)
#define DIM_M 512
#define DIM_K 4096
#define DIM_N 11008

#define CTA_M 128
#define CTA_N 128
#define KSTEP 64                 // halves per K step
#define SPLITK 4
#define K_PER (DIM_K / SPLITK)   // 1024
#define ITERS (K_PER / KSTEP)    // 16
#define STAGES 3
#define GRID_MT (DIM_M / CTA_M)  // 4
#define GRID_NT (DIM_N / CTA_N)  // 86

// SMEM rows padded to 144B -> 8-row ldmatrix bases distinct mod 128 (conflict-free)
#define ROWB 144
#define A_TILE (128 * ROWB)                  // 18432
#define B_TILE (128 * ROWB)                  // 18432
#define STAGE_BYTES (A_TILE + B_TILE)        // 36864
#define SMEM_TOTAL (STAGES * STAGE_BYTES)    // 110592 (x2 CTAs = 221184 <= 228KB)

// x converted to fp16, row-major [512][4096]
__device__ __align__(16) __half g_x16[DIM_M * DIM_K];
// weights dequantized to fp16, row-major [11008][4096]
__device__ __align__(16) __half g_w16[(size_t)DIM_N * DIM_K];
// split-K fp16 partials [SPLITK][512][11008]
__device__ __align__(16) __half g_partial[(size_t)SPLITK * DIM_M * DIM_N];

__device__ __forceinline__ uint32_t smem_u32(const void* p) {
    uint32_t a;
    asm("{ .reg .u64 t; cvta.to.shared.u64 t, %1; cvt.u32.u64 %0, t; }" : "=r"(a) : "l"(p));
    return a;
}

__device__ __forceinline__ void cp_async16(uint32_t dst, const void* src) {
    asm volatile("cp.async.cg.shared.global [%0], [%1], 16;" :: "r"(dst), "l"(src));
}
__device__ __forceinline__ void cp_commit() { asm volatile("cp.async.commit_group;"); }

__device__ __forceinline__ void ldsm4(uint32_t* r, uint32_t addr) {
    asm volatile("ldmatrix.sync.aligned.m8n8.x4.shared.b16 {%0,%1,%2,%3}, [%4];"
                 : "=r"(r[0]), "=r"(r[1]), "=r"(r[2]), "=r"(r[3]) : "r"(addr));
}

__device__ __forceinline__ void mma16816(float* d, const uint32_t* a, const uint32_t* b) {
    asm volatile(
        "mma.sync.aligned.m16n8k16.row.col.f32.f16.f16.f32 "
        "{%0,%1,%2,%3}, {%4,%5,%6,%7}, {%8,%9}, {%0,%1,%2,%3};"
        : "+f"(d[0]), "+f"(d[1]), "+f"(d[2]), "+f"(d[3])
        : "r"(a[0]), "r"(a[1]), "r"(a[2]), "r"(a[3]), "r"(b[0]), "r"(b[1]));
}

__device__ __forceinline__ uint32_t pack2(float a, float b) {
    __half2 h = __floats2half2_rn(a, b);
    return *reinterpret_cast<uint32_t*>(&h);
}

// ---------------- kernel 0: x fp32 -> fp16 row-major ----------------
__global__ void __launch_bounds__(256) convert_x_kernel(const float* __restrict__ x) {
    int gid = blockIdx.x * blockDim.x + threadIdx.x;
    const float4* src = reinterpret_cast<const float4*>(x) + gid * 2;
    float4 f0 = __ldg(src);
    float4 f1 = __ldg(src + 1);
    uint4 v;
    v.x = pack2(f0.x, f0.y);
    v.y = pack2(f0.z, f0.w);
    v.z = pack2(f1.x, f1.y);
    v.w = pack2(f1.z, f1.w);
    reinterpret_cast<uint4*>(g_x16)[gid] = v;
}

// ---------------- kernel 1: dequant weights int32(4bit codes) -> fp16 ----------------
__global__ void __launch_bounds__(256) dequant_w_kernel(const int* __restrict__ w,
                                                        const float* __restrict__ saz) {
    int gid = blockIdx.x * blockDim.x + threadIdx.x;   // N*K/8 threads
    int n = gid >> 9;                // DIM_K/8 = 512 chunks per row
    int kc = (gid & 511) << 3;
    int g = kc >> 7;                 // group of 128
    float2 sz = __ldg(reinterpret_cast<const float2*>(saz) + (size_t)g * DIM_N + n);
    const float s = sz.x, z = sz.y;
    const int4* src = reinterpret_cast<const int4*>(w + (size_t)n * DIM_K + kc);
    int4 a = __ldg(src);
    int4 b = __ldg(src + 1);
    uint4 v;
    v.x = pack2((float)(a.x - 8) * s + z, (float)(a.y - 8) * s + z);
    v.y = pack2((float)(a.z - 8) * s + z, (float)(a.w - 8) * s + z);
    v.z = pack2((float)(b.x - 8) * s + z, (float)(b.y - 8) * s + z);
    v.w = pack2((float)(b.z - 8) * s + z, (float)(b.w - 8) * s + z);
    reinterpret_cast<uint4*>(g_w16)[gid] = v;
}

// ---------------- kernel 2: fp16 HMMA GEMM, split-K x4, warp tile 64x32 ----------------
__global__ void __launch_bounds__(256, 2) gemm_kernel() {
    extern __shared__ __align__(1024) char smem[];
    const uint32_t sb = smem_u32(smem);
    const int tid = threadIdx.x;
    const int wid = tid >> 5;
    const int lid = tid & 31;

    // decode: mtile fastest (4), then kq (4), then ntile -> 16 adjacent CTAs share a B slab
    const int mtile = blockIdx.x & 3;
    const int kq = (blockIdx.x >> 2) & 3;
    const int ntile = blockIdx.x >> 4;
    const int mbase = mtile * CTA_M;
    const int nbase = ntile * CTA_N;
    const int kbase = kq * K_PER;

    // 2x4 warp grid, warp tile 64x32 (4 m16 sub-tiles per warp)
    const int m0w = (wid & 1) * 64;
    const int n0w = (wid >> 1) * 32;

    // ---- loaders: each tile 128 rows x 8 chunks(16B) = 1024 chunks; 4 chunks/thread ----
    const int r0 = tid >> 3;         // 0..31
    const int c  = tid & 7;          // 0..7
    const __half* aG = g_x16 + (size_t)(mbase + r0) * DIM_K + kbase + c * 8;
    const __half* bG = g_w16 + (size_t)(nbase + r0) * DIM_K + kbase + c * 8;
    const uint32_t ld_off = (uint32_t)r0 * ROWB + c * 16;
    const size_t gstep32 = (size_t)32 * DIM_K;
    const uint32_t sstep32 = 32u * ROWB;

    // ---- ldmatrix lane bases ----
    const uint32_t a_lane_off = (uint32_t)(m0w + (lid & 15)) * ROWB + ((lid >> 4) << 4);
    const uint32_t b_lane_off = (uint32_t)(n0w + (lid & 7) + ((lid >> 4) & 1) * 8) * ROWB
                                + (((lid >> 3) & 1) << 4);

    float d[4][4][4];
    #pragma unroll
    for (int i = 0; i < 4; ++i)
        #pragma unroll
        for (int j = 0; j < 4; ++j)
            #pragma unroll
            for (int k = 0; k < 4; ++k) d[i][j][k] = 0.f;

    #define ISSUE_STAGE(ks, buf) do {                                     \
        const uint32_t stA = sb + (buf) * STAGE_BYTES + ld_off;           \
        const __half* sa = aG + (ks) * KSTEP;                             \
        cp_async16(stA,               sa);                                \
        cp_async16(stA + sstep32,     sa + gstep32);                      \
        cp_async16(stA + 2 * sstep32, sa + 2 * gstep32);                  \
        cp_async16(stA + 3 * sstep32, sa + 3 * gstep32);                  \
        const uint32_t stB = stA + A_TILE;                                \
        const __half* sbp = bG + (ks) * KSTEP;                            \
        cp_async16(stB,               sbp);                               \
        cp_async16(stB + sstep32,     sbp + gstep32);                     \
        cp_async16(stB + 2 * sstep32, sbp + 2 * gstep32);                 \
        cp_async16(stB + 3 * sstep32, sbp + 3 * gstep32);                 \
    } while (0)

    // ---- prologue: stages 0..1 in flight ----
    #pragma unroll
    for (int s = 0; s < STAGES - 1; ++s) { ISSUE_STAGE(s, s); cp_commit(); }

    int buf = 0;
    for (int ks = 0; ks < ITERS; ++ks) {
        asm volatile("cp.async.wait_group %0;" :: "n"(STAGES - 2));
        __syncthreads();

        // issue into the buffer consumed at iteration ks-1 (sync above certified it free)
        const int pf = ks + STAGES - 1;
        if (pf < ITERS) {
            const int pbuf = (buf + STAGES - 1) % STAGES;
            ISSUE_STAGE(pf, pbuf);
        }
        cp_commit();

        const uint32_t aBase = sb + buf * STAGE_BYTES + a_lane_off;
        const uint32_t bBase = sb + buf * STAGE_BYTES + A_TILE + b_lane_off;
        #pragma unroll
        for (int kc = 0; kc < 4; ++kc) {
            uint32_t a[4][4], b[4][2];
            #pragma unroll
            for (int mt = 0; mt < 4; ++mt)
                ldsm4(a[mt], aBase + (uint32_t)mt * (16 * ROWB) + kc * 32);
            #pragma unroll
            for (int nt = 0; nt < 2; ++nt) {
                uint32_t t[4];
                ldsm4(t, bBase + (uint32_t)nt * (16 * ROWB) + kc * 32);
                b[2 * nt][0] = t[0]; b[2 * nt][1] = t[1];
                b[2 * nt + 1][0] = t[2]; b[2 * nt + 1][1] = t[3];
            }
            #pragma unroll
            for (int mt = 0; mt < 4; ++mt)
                #pragma unroll
                for (int n8 = 0; n8 < 4; ++n8)
                    mma16816(d[mt][n8], a[mt], b[n8]);
        }

        if (++buf == STAGES) buf = 0;
    }

    // ---- epilogue: registers -> fp16 split-K partial ----
    __half* pout = g_partial + (size_t)kq * DIM_M * DIM_N;
    const int g = lid >> 2;
    const int tc = (lid & 3) * 2;
    #pragma unroll
    for (int mt = 0; mt < 4; ++mt) {
        const int row0 = mbase + m0w + mt * 16 + g;
        #pragma unroll
        for (int n8 = 0; n8 < 4; ++n8) {
            const int col = nbase + n0w + n8 * 8 + tc;
            *reinterpret_cast<uint32_t*>(pout + (size_t)row0 * DIM_N + col) =
                pack2(d[mt][n8][0], d[mt][n8][1]);
            *reinterpret_cast<uint32_t*>(pout + (size_t)(row0 + 8) * DIM_N + col) =
                pack2(d[mt][n8][2], d[mt][n8][3]);
        }
    }
}

// ---------------- kernel 3: sum fp16 split-K partials -> fp32 out ----------------
__global__ void __launch_bounds__(256) reduce_kernel(float* __restrict__ out) {
    const size_t gid = (size_t)blockIdx.x * blockDim.x + threadIdx.x;  // per 8 halves
    const uint4* p = reinterpret_cast<const uint4*>(g_partial);
    const size_t q = (size_t)DIM_M * DIM_N / 8;
    uint4 v[SPLITK];
    v[0] = p[gid];
    v[1] = p[gid + q];
    v[2] = p[gid + 2 * q];
    v[3] = p[gid + 3 * q];
    float acc[8];
    #pragma unroll
    for (int i = 0; i < 8; ++i) acc[i] = 0.f;
    #pragma unroll
    for (int s = 0; s < SPLITK; ++s) {
        const uint32_t* u = reinterpret_cast<const uint32_t*>(&v[s]);
        #pragma unroll
        for (int j = 0; j < 4; ++j) {
            __half2 h = *reinterpret_cast<const __half2*>(&u[j]);
            float2 f = __half22float2(h);
            acc[2 * j] += f.x;
            acc[2 * j + 1] += f.y;
        }
    }
    float4 r0, r1;
    r0.x = acc[0]; r0.y = acc[1]; r0.z = acc[2]; r0.w = acc[3];
    r1.x = acc[4]; r1.y = acc[5]; r1.z = acc[6]; r1.w = acc[7];
    reinterpret_cast<float4*>(out)[2 * gid] = r0;
    reinterpret_cast<float4*>(out)[2 * gid + 1] = r1;
}

extern "C" void kernel_launch(void* const* d_in, const int* in_sizes, int n_in,
                              void* d_out, int out_size) {
    const float* x   = (const float*)d_in[0];
    const int*   w   = (const int*)d_in[1];
    const float* saz = (const float*)d_in[2];
    float* out = (float*)d_out;

    cudaFuncSetAttribute(gemm_kernel, cudaFuncAttributeMaxDynamicSharedMemorySize, SMEM_TOTAL);

    convert_x_kernel<<<(DIM_M * DIM_K / 8) / 256, 256>>>(x);
    dequant_w_kernel<<<((size_t)DIM_N * DIM_K / 8) / 256, 256>>>(w, saz);
    gemm_kernel<<<GRID_MT * GRID_NT * SPLITK, 256, SMEM_TOTAL>>>();
    reduce_kernel<<<(DIM_M * DIM_N / 8) / 256, 256>>>(out);
}

// round 13
// speedup vs baseline: 1.1644x; 1.0039x over previous
#include <cuda_runtime.h>
#include <cuda_fp16.h>
#include <cstdint>

// Problem dims (fixed per reference)
#define DIM_M 512
#define DIM_K 4096
#define DIM_N 11008

#define CTA_M 128
#define CTA_N 128
#define KSTEP 64                 // halves per K step
#define SPLITK 4
#define K_PER (DIM_K / SPLITK)   // 1024
#define ITERS (K_PER / KSTEP)    // 16
#define STAGES 3
#define GRID_MT (DIM_M / CTA_M)  // 4
#define GRID_NT (DIM_N / CTA_N)  // 86

// SMEM rows padded to 144B -> 8-row ldmatrix bases distinct mod 128 (conflict-free)
#define ROWB 144
#define A_TILE (128 * ROWB)                  // 18432
#define B_TILE (128 * ROWB)                  // 18432
#define STAGE_BYTES (A_TILE + B_TILE)        // 36864
#define SMEM_TOTAL (STAGES * STAGE_BYTES)    // 110592 (x2 CTAs = 221184 <= 228KB)

// pre-pass block split
#define DQ_BLOCKS (int)(((size_t)DIM_N * DIM_K / 8) / 256)   // 22016
#define CV_BLOCKS ((DIM_M * DIM_K / 8) / 256)                // 1024

// x converted to fp16, row-major [512][4096]
__device__ __align__(16) __half g_x16[DIM_M * DIM_K];
// weights dequantized to fp16, row-major [11008][4096]
__device__ __align__(16) __half g_w16[(size_t)DIM_N * DIM_K];
// split-K fp16 partials [SPLITK][512][11008]
__device__ __align__(16) __half g_partial[(size_t)SPLITK * DIM_M * DIM_N];

__device__ __forceinline__ uint32_t smem_u32(const void* p) {
    uint32_t a;
    asm("{ .reg .u64 t; cvta.to.shared.u64 t, %1; cvt.u32.u64 %0, t; }" : "=r"(a) : "l"(p));
    return a;
}

__device__ __forceinline__ void cp_async16(uint32_t dst, const void* src) {
    asm volatile("cp.async.cg.shared.global [%0], [%1], 16;" :: "r"(dst), "l"(src));
}
__device__ __forceinline__ void cp_commit() { asm volatile("cp.async.commit_group;"); }

__device__ __forceinline__ void ldsm4(uint32_t* r, uint32_t addr) {
    asm volatile("ldmatrix.sync.aligned.m8n8.x4.shared.b16 {%0,%1,%2,%3}, [%4];"
                 : "=r"(r[0]), "=r"(r[1]), "=r"(r[2]), "=r"(r[3]) : "r"(addr));
}

__device__ __forceinline__ void mma16816(float* d, const uint32_t* a, const uint32_t* b) {
    asm volatile(
        "mma.sync.aligned.m16n8k16.row.col.f32.f16.f16.f32 "
        "{%0,%1,%2,%3}, {%4,%5,%6,%7}, {%8,%9}, {%0,%1,%2,%3};"
        : "+f"(d[0]), "+f"(d[1]), "+f"(d[2]), "+f"(d[3])
        : "r"(a[0]), "r"(a[1]), "r"(a[2]), "r"(a[3]), "r"(b[0]), "r"(b[1]));
}

__device__ __forceinline__ uint32_t pack2(float a, float b) {
    __half2 h = __floats2half2_rn(a, b);
    return *reinterpret_cast<uint32_t*>(&h);
}

// ---------------- kernel 0: fused pre-pass ----------------
// blocks [0, DQ_BLOCKS): dequant weights int32 codes -> fp16
// blocks [DQ_BLOCKS, DQ_BLOCKS+CV_BLOCKS): convert x fp32 -> fp16
__global__ void __launch_bounds__(256) prepass_kernel(const float* __restrict__ x,
                                                      const int* __restrict__ w,
                                                      const float* __restrict__ saz) {
    if (blockIdx.x < DQ_BLOCKS) {
        int gid = blockIdx.x * blockDim.x + threadIdx.x;   // N*K/8 threads
        int n = gid >> 9;                // DIM_K/8 = 512 chunks per row
        int kc = (gid & 511) << 3;
        int g = kc >> 7;                 // group of 128
        float2 sz = __ldg(reinterpret_cast<const float2*>(saz) + (size_t)g * DIM_N + n);
        const float s = sz.x, z = sz.y;
        const int4* src = reinterpret_cast<const int4*>(w + (size_t)n * DIM_K + kc);
        int4 a = __ldg(src);
        int4 b = __ldg(src + 1);
        uint4 v;
        v.x = pack2((float)(a.x - 8) * s + z, (float)(a.y - 8) * s + z);
        v.y = pack2((float)(a.z - 8) * s + z, (float)(a.w - 8) * s + z);
        v.z = pack2((float)(b.x - 8) * s + z, (float)(b.y - 8) * s + z);
        v.w = pack2((float)(b.z - 8) * s + z, (float)(b.w - 8) * s + z);
        reinterpret_cast<uint4*>(g_w16)[gid] = v;
    } else {
        int gid = (blockIdx.x - DQ_BLOCKS) * blockDim.x + threadIdx.x;
        const float4* src = reinterpret_cast<const float4*>(x) + gid * 2;
        float4 f0 = __ldg(src);
        float4 f1 = __ldg(src + 1);
        uint4 v;
        v.x = pack2(f0.x, f0.y);
        v.y = pack2(f0.z, f0.w);
        v.z = pack2(f1.x, f1.y);
        v.w = pack2(f1.z, f1.w);
        reinterpret_cast<uint4*>(g_x16)[gid] = v;
    }
}

// ---------------- kernel 1: fp16 HMMA GEMM, split-K x4, warp tile 64x32 ----------------
__global__ void __launch_bounds__(256, 2) gemm_kernel() {
    extern __shared__ __align__(1024) char smem[];
    const uint32_t sb = smem_u32(smem);
    const int tid = threadIdx.x;
    const int wid = tid >> 5;
    const int lid = tid & 31;

    // decode: mtile fastest (4), then kq (4), then ntile -> 16 adjacent CTAs share a B slab
    const int mtile = blockIdx.x & 3;
    const int kq = (blockIdx.x >> 2) & 3;
    const int ntile = blockIdx.x >> 4;
    const int mbase = mtile * CTA_M;
    const int nbase = ntile * CTA_N;
    const int kbase = kq * K_PER;

    // 2x4 warp grid, warp tile 64x32 (4 m16 sub-tiles per warp)
    const int m0w = (wid & 1) * 64;
    const int n0w = (wid >> 1) * 32;

    // ---- loaders: each tile 128 rows x 8 chunks(16B) = 1024 chunks; 4 chunks/thread ----
    const int r0 = tid >> 3;         // 0..31
    const int c  = tid & 7;          // 0..7
    const __half* aG = g_x16 + (size_t)(mbase + r0) * DIM_K + kbase + c * 8;
    const __half* bG = g_w16 + (size_t)(nbase + r0) * DIM_K + kbase + c * 8;
    const uint32_t ld_off = (uint32_t)r0 * ROWB + c * 16;
    const size_t gstep32 = (size_t)32 * DIM_K;
    const uint32_t sstep32 = 32u * ROWB;

    // ---- ldmatrix lane bases ----
    const uint32_t a_lane_off = (uint32_t)(m0w + (lid & 15)) * ROWB + ((lid >> 4) << 4);
    const uint32_t b_lane_off = (uint32_t)(n0w + (lid & 7) + ((lid >> 4) & 1) * 8) * ROWB
                                + (((lid >> 3) & 1) << 4);

    float d[4][4][4];
    #pragma unroll
    for (int i = 0; i < 4; ++i)
        #pragma unroll
        for (int j = 0; j < 4; ++j)
            #pragma unroll
            for (int k = 0; k < 4; ++k) d[i][j][k] = 0.f;

    #define ISSUE_STAGE(ks, buf) do {                                     \
        const uint32_t stA = sb + (buf) * STAGE_BYTES + ld_off;           \
        const __half* sa = aG + (ks) * KSTEP;                             \
        cp_async16(stA,               sa);                                \
        cp_async16(stA + sstep32,     sa + gstep32);                      \
        cp_async16(stA + 2 * sstep32, sa + 2 * gstep32);                  \
        cp_async16(stA + 3 * sstep32, sa + 3 * gstep32);                  \
        const uint32_t stB = stA + A_TILE;                                \
        const __half* sbp = bG + (ks) * KSTEP;                            \
        cp_async16(stB,               sbp);                               \
        cp_async16(stB + sstep32,     sbp + gstep32);                     \
        cp_async16(stB + 2 * sstep32, sbp + 2 * gstep32);                 \
        cp_async16(stB + 3 * sstep32, sbp + 3 * gstep32);                 \
    } while (0)

    // ---- prologue: stages 0..1 in flight ----
    #pragma unroll
    for (int s = 0; s < STAGES - 1; ++s) { ISSUE_STAGE(s, s); cp_commit(); }

    int buf = 0;
    for (int ks = 0; ks < ITERS; ++ks) {
        asm volatile("cp.async.wait_group %0;" :: "n"(STAGES - 2));
        __syncthreads();

        // issue into the buffer consumed at iteration ks-1 (sync above certified it free)
        const int pf = ks + STAGES - 1;
        if (pf < ITERS) {
            const int pbuf = (buf + STAGES - 1) % STAGES;
            ISSUE_STAGE(pf, pbuf);
        }
        cp_commit();

        const uint32_t aBase = sb + buf * STAGE_BYTES + a_lane_off;
        const uint32_t bBase = sb + buf * STAGE_BYTES + A_TILE + b_lane_off;
        #pragma unroll
        for (int kc = 0; kc < 4; ++kc) {
            uint32_t a[4][4], b[4][2];
            #pragma unroll
            for (int mt = 0; mt < 4; ++mt)
                ldsm4(a[mt], aBase + (uint32_t)mt * (16 * ROWB) + kc * 32);
            #pragma unroll
            for (int nt = 0; nt < 2; ++nt) {
                uint32_t t[4];
                ldsm4(t, bBase + (uint32_t)nt * (16 * ROWB) + kc * 32);
                b[2 * nt][0] = t[0]; b[2 * nt][1] = t[1];
                b[2 * nt + 1][0] = t[2]; b[2 * nt + 1][1] = t[3];
            }
            #pragma unroll
            for (int mt = 0; mt < 4; ++mt)
                #pragma unroll
                for (int n8 = 0; n8 < 4; ++n8)
                    mma16816(d[mt][n8], a[mt], b[n8]);
        }

        if (++buf == STAGES) buf = 0;
    }

    // ---- epilogue: registers -> fp16 split-K partial (evict-first: read once later) ----
    __half* pout = g_partial + (size_t)kq * DIM_M * DIM_N;
    const int g = lid >> 2;
    const int tc = (lid & 3) * 2;
    #pragma unroll
    for (int mt = 0; mt < 4; ++mt) {
        const int row0 = mbase + m0w + mt * 16 + g;
        #pragma unroll
        for (int n8 = 0; n8 < 4; ++n8) {
            const int col = nbase + n0w + n8 * 8 + tc;
            uint32_t lo = pack2(d[mt][n8][0], d[mt][n8][1]);
            uint32_t hi = pack2(d[mt][n8][2], d[mt][n8][3]);
            asm volatile("st.global.cs.u32 [%0], %1;"
                         :: "l"(pout + (size_t)row0 * DIM_N + col), "r"(lo) : "memory");
            asm volatile("st.global.cs.u32 [%0], %1;"
                         :: "l"(pout + (size_t)(row0 + 8) * DIM_N + col), "r"(hi) : "memory");
        }
    }
}

// ---------------- kernel 2: sum fp16 split-K partials -> fp32 out ----------------
__global__ void __launch_bounds__(256) reduce_kernel(float* __restrict__ out) {
    const size_t gid = (size_t)blockIdx.x * blockDim.x + threadIdx.x;  // per 8 halves
    const uint4* p = reinterpret_cast<const uint4*>(g_partial);
    const size_t q = (size_t)DIM_M * DIM_N / 8;
    uint4 v[SPLITK];
    v[0] = __ldcs(p + gid);
    v[1] = __ldcs(p + gid + q);
    v[2] = __ldcs(p + gid + 2 * q);
    v[3] = __ldcs(p + gid + 3 * q);
    float acc[8];
    #pragma unroll
    for (int i = 0; i < 8; ++i) acc[i] = 0.f;
    #pragma unroll
    for (int s = 0; s < SPLITK; ++s) {
        const uint32_t* u = reinterpret_cast<const uint32_t*>(&v[s]);
        #pragma unroll
        for (int j = 0; j < 4; ++j) {
            __half2 h = *reinterpret_cast<const __half2*>(&u[j]);
            float2 f = __half22float2(h);
            acc[2 * j] += f.x;
            acc[2 * j + 1] += f.y;
        }
    }
    float4 r0, r1;
    r0.x = acc[0]; r0.y = acc[1]; r0.z = acc[2]; r0.w = acc[3];
    r1.x = acc[4]; r1.y = acc[5]; r1.z = acc[6]; r1.w = acc[7];
    reinterpret_cast<float4*>(out)[2 * gid] = r0;
    reinterpret_cast<float4*>(out)[2 * gid + 1] = r1;
}

extern "C" void kernel_launch(void* const* d_in, const int* in_sizes, int n_in,
                              void* d_out, int out_size) {
    const float* x   = (const float*)d_in[0];
    const int*   w   = (const int*)d_in[1];
    const float* saz = (const float*)d_in[2];
    float* out = (float*)d_out;

    cudaFuncSetAttribute(gemm_kernel, cudaFuncAttributeMaxDynamicSharedMemorySize, SMEM_TOTAL);

    prepass_kernel<<<DQ_BLOCKS + CV_BLOCKS, 256>>>(x, w, saz);
    gemm_kernel<<<GRID_MT * GRID_NT * SPLITK, 256, SMEM_TOTAL>>>();
    reduce_kernel<<<(DIM_M * DIM_N / 8) / 256, 256>>>(out);
}

// round 14
// speedup vs baseline: 1.1656x; 1.0010x over previous
#include <cuda_runtime.h>
#include <cuda_fp16.h>
#include <cstdint>

// Problem dims (fixed per reference)
#define DIM_M 512
#define DIM_K 4096
#define DIM_N 11008

#define CTA_M 128
#define CTA_N 128
#define KSTEP 64                 // halves per K step
#define SPLITK 4
#define K_PER (DIM_K / SPLITK)   // 1024
#define ITERS (K_PER / KSTEP)    // 16
#define STAGES 3
#define GRID_MT (DIM_M / CTA_M)  // 4
#define GRID_NT (DIM_N / CTA_N)  // 86

// SMEM rows padded to 144B -> 8-row ldmatrix bases distinct mod 128 (conflict-free)
#define ROWB 144
#define A_TILE (128 * ROWB)                  // 18432
#define B_TILE (128 * ROWB)                  // 18432
#define STAGE_BYTES (A_TILE + B_TILE)        // 36864
#define SMEM_TOTAL (STAGES * STAGE_BYTES)    // 110592 (x2 CTAs = 221184 <= 228KB)

// pre-pass block split
#define DQ_BLOCKS (int)(((size_t)DIM_N * DIM_K / 8) / 256)   // 22016
#define CV_BLOCKS ((DIM_M * DIM_K / 8) / 256)                // 1024

// x converted to fp16, row-major [512][4096]
__device__ __align__(16) __half g_x16[DIM_M * DIM_K];
// weights dequantized to fp16, row-major [11008][4096]
__device__ __align__(16) __half g_w16[(size_t)DIM_N * DIM_K];
// split-K fp16 partials [SPLITK][512][11008]
__device__ __align__(16) __half g_partial[(size_t)SPLITK * DIM_M * DIM_N];

__device__ __forceinline__ uint32_t smem_u32(const void* p) {
    uint32_t a;
    asm("{ .reg .u64 t; cvta.to.shared.u64 t, %1; cvt.u32.u64 %0, t; }" : "=r"(a) : "l"(p));
    return a;
}

__device__ __forceinline__ void cp_async16(uint32_t dst, const void* src) {
    asm volatile("cp.async.cg.shared.global [%0], [%1], 16;" :: "r"(dst), "l"(src));
}
__device__ __forceinline__ void cp_commit() { asm volatile("cp.async.commit_group;"); }

__device__ __forceinline__ void ldsm4(uint32_t* r, uint32_t addr) {
    asm volatile("ldmatrix.sync.aligned.m8n8.x4.shared.b16 {%0,%1,%2,%3}, [%4];"
                 : "=r"(r[0]), "=r"(r[1]), "=r"(r[2]), "=r"(r[3]) : "r"(addr));
}

__device__ __forceinline__ void mma16816(float* d, const uint32_t* a, const uint32_t* b) {
    asm volatile(
        "mma.sync.aligned.m16n8k16.row.col.f32.f16.f16.f32 "
        "{%0,%1,%2,%3}, {%4,%5,%6,%7}, {%8,%9}, {%0,%1,%2,%3};"
        : "+f"(d[0]), "+f"(d[1]), "+f"(d[2]), "+f"(d[3])
        : "r"(a[0]), "r"(a[1]), "r"(a[2]), "r"(a[3]), "r"(b[0]), "r"(b[1]));
}

__device__ __forceinline__ uint32_t pack2(float a, float b) {
    __half2 h = __floats2half2_rn(a, b);
    return *reinterpret_cast<uint32_t*>(&h);
}

// ---------------- kernel 0: fused pre-pass ----------------
// blocks [0, DQ_BLOCKS): dequant weights int32 codes -> fp16
// blocks [DQ_BLOCKS, DQ_BLOCKS+CV_BLOCKS): convert x fp32 -> fp16
__global__ void __launch_bounds__(256) prepass_kernel(const float* __restrict__ x,
                                                      const int* __restrict__ w,
                                                      const float* __restrict__ saz) {
    if (blockIdx.x < DQ_BLOCKS) {
        int gid = blockIdx.x * blockDim.x + threadIdx.x;   // N*K/8 threads
        int n = gid >> 9;                // DIM_K/8 = 512 chunks per row
        int kc = (gid & 511) << 3;
        int g = kc >> 7;                 // group of 128
        float2 sz = __ldg(reinterpret_cast<const float2*>(saz) + (size_t)g * DIM_N + n);
        const float s = sz.x, z = sz.y;
        const int4* src = reinterpret_cast<const int4*>(w + (size_t)n * DIM_K + kc);
        int4 a = __ldg(src);
        int4 b = __ldg(src + 1);
        uint4 v;
        v.x = pack2((float)(a.x - 8) * s + z, (float)(a.y - 8) * s + z);
        v.y = pack2((float)(a.z - 8) * s + z, (float)(a.w - 8) * s + z);
        v.z = pack2((float)(b.x - 8) * s + z, (float)(b.y - 8) * s + z);
        v.w = pack2((float)(b.z - 8) * s + z, (float)(b.w - 8) * s + z);
        reinterpret_cast<uint4*>(g_w16)[gid] = v;
    } else {
        int gid = (blockIdx.x - DQ_BLOCKS) * blockDim.x + threadIdx.x;
        const float4* src = reinterpret_cast<const float4*>(x) + gid * 2;
        float4 f0 = __ldg(src);
        float4 f1 = __ldg(src + 1);
        uint4 v;
        v.x = pack2(f0.x, f0.y);
        v.y = pack2(f0.z, f0.w);
        v.z = pack2(f1.x, f1.y);
        v.w = pack2(f1.z, f1.w);
        reinterpret_cast<uint4*>(g_x16)[gid] = v;
    }
}

// ---------------- kernel 1: fp16 HMMA GEMM, split-K x4, warp tile 64x32 ----------------
__global__ void __launch_bounds__(256, 2) gemm_kernel() {
    extern __shared__ __align__(1024) char smem[];
    const uint32_t sb = smem_u32(smem);
    const int tid = threadIdx.x;
    const int wid = tid >> 5;
    const int lid = tid & 31;

    // decode: mtile fastest (4), then kq (4), then ntile -> 16 adjacent CTAs share a B slab
    const int mtile = blockIdx.x & 3;
    const int kq = (blockIdx.x >> 2) & 3;
    const int ntile = blockIdx.x >> 4;
    const int mbase = mtile * CTA_M;
    const int nbase = ntile * CTA_N;
    const int kbase = kq * K_PER;

    // 2x4 warp grid, warp tile 64x32 (4 m16 sub-tiles per warp)
    const int m0w = (wid & 1) * 64;
    const int n0w = (wid >> 1) * 32;

    // ---- loaders: each tile 128 rows x 8 chunks(16B) = 1024 chunks; 4 chunks/thread ----
    const int r0 = tid >> 3;         // 0..31
    const int c  = tid & 7;          // 0..7
    const __half* aG = g_x16 + (size_t)(mbase + r0) * DIM_K + kbase + c * 8;
    const __half* bG = g_w16 + (size_t)(nbase + r0) * DIM_K + kbase + c * 8;
    const uint32_t ld_off = (uint32_t)r0 * ROWB + c * 16;
    const size_t gstep32 = (size_t)32 * DIM_K;
    const uint32_t sstep32 = 32u * ROWB;

    // ---- ldmatrix lane bases ----
    const uint32_t a_lane_off = (uint32_t)(m0w + (lid & 15)) * ROWB + ((lid >> 4) << 4);
    const uint32_t b_lane_off = (uint32_t)(n0w + (lid & 7) + ((lid >> 4) & 1) * 8) * ROWB
                                + (((lid >> 3) & 1) << 4);

    float d[4][4][4];
    #pragma unroll
    for (int i = 0; i < 4; ++i)
        #pragma unroll
        for (int j = 0; j < 4; ++j)
            #pragma unroll
            for (int k = 0; k < 4; ++k) d[i][j][k] = 0.f;

    #define ISSUE_STAGE(ks, buf) do {                                     \
        const uint32_t stA = sb + (buf) * STAGE_BYTES + ld_off;           \
        const __half* sa = aG + (ks) * KSTEP;                             \
        cp_async16(stA,               sa);                                \
        cp_async16(stA + sstep32,     sa + gstep32);                      \
        cp_async16(stA + 2 * sstep32, sa + 2 * gstep32);                  \
        cp_async16(stA + 3 * sstep32, sa + 3 * gstep32);                  \
        const uint32_t stB = stA + A_TILE;                                \
        const __half* sbp = bG + (ks) * KSTEP;                            \
        cp_async16(stB,               sbp);                               \
        cp_async16(stB + sstep32,     sbp + gstep32);                     \
        cp_async16(stB + 2 * sstep32, sbp + 2 * gstep32);                 \
        cp_async16(stB + 3 * sstep32, sbp + 3 * gstep32);                 \
    } while (0)

    // ---- prologue: stages 0..1 in flight ----
    #pragma unroll
    for (int s = 0; s < STAGES - 1; ++s) { ISSUE_STAGE(s, s); cp_commit(); }

    int buf = 0;
    for (int ks = 0; ks < ITERS; ++ks) {
        asm volatile("cp.async.wait_group %0;" :: "n"(STAGES - 2));
        __syncthreads();

        // issue into the buffer consumed at iteration ks-1 (sync above certified it free)
        const int pf = ks + STAGES - 1;
        if (pf < ITERS) {
            const int pbuf = (buf + STAGES - 1) % STAGES;
            ISSUE_STAGE(pf, pbuf);
        }
        cp_commit();

        const uint32_t aBase = sb + buf * STAGE_BYTES + a_lane_off;
        const uint32_t bBase = sb + buf * STAGE_BYTES + A_TILE + b_lane_off;
        #pragma unroll
        for (int kc = 0; kc < 4; ++kc) {
            uint32_t a[4][4], b[4][2];
            #pragma unroll
            for (int mt = 0; mt < 4; ++mt)
                ldsm4(a[mt], aBase + (uint32_t)mt * (16 * ROWB) + kc * 32);
            #pragma unroll
            for (int nt = 0; nt < 2; ++nt) {
                uint32_t t[4];
                ldsm4(t, bBase + (uint32_t)nt * (16 * ROWB) + kc * 32);
                b[2 * nt][0] = t[0]; b[2 * nt][1] = t[1];
                b[2 * nt + 1][0] = t[2]; b[2 * nt + 1][1] = t[3];
            }
            #pragma unroll
            for (int mt = 0; mt < 4; ++mt)
                #pragma unroll
                for (int n8 = 0; n8 < 4; ++n8)
                    mma16816(d[mt][n8], a[mt], b[n8]);
        }

        if (++buf == STAGES) buf = 0;
    }

    // ---- epilogue: registers -> fp16 split-K partial (plain stores; .cs measured -14us) ----
    __half* pout = g_partial + (size_t)kq * DIM_M * DIM_N;
    const int g = lid >> 2;
    const int tc = (lid & 3) * 2;
    #pragma unroll
    for (int mt = 0; mt < 4; ++mt) {
        const int row0 = mbase + m0w + mt * 16 + g;
        #pragma unroll
        for (int n8 = 0; n8 < 4; ++n8) {
            const int col = nbase + n0w + n8 * 8 + tc;
            *reinterpret_cast<uint32_t*>(pout + (size_t)row0 * DIM_N + col) =
                pack2(d[mt][n8][0], d[mt][n8][1]);
            *reinterpret_cast<uint32_t*>(pout + (size_t)(row0 + 8) * DIM_N + col) =
                pack2(d[mt][n8][2], d[mt][n8][3]);
        }
    }
}

// ---------------- kernel 2: sum fp16 split-K partials -> fp32 out ----------------
__global__ void __launch_bounds__(256) reduce_kernel(float* __restrict__ out) {
    const size_t gid = (size_t)blockIdx.x * blockDim.x + threadIdx.x;  // per 8 halves
    const uint4* p = reinterpret_cast<const uint4*>(g_partial);
    const size_t q = (size_t)DIM_M * DIM_N / 8;
    uint4 v[SPLITK];
    v[0] = __ldcs(p + gid);
    v[1] = __ldcs(p + gid + q);
    v[2] = __ldcs(p + gid + 2 * q);
    v[3] = __ldcs(p + gid + 3 * q);
    float acc[8];
    #pragma unroll
    for (int i = 0; i < 8; ++i) acc[i] = 0.f;
    #pragma unroll
    for (int s = 0; s < SPLITK; ++s) {
        const uint32_t* u = reinterpret_cast<const uint32_t*>(&v[s]);
        #pragma unroll
        for (int j = 0; j < 4; ++j) {
            __half2 h = *reinterpret_cast<const __half2*>(&u[j]);
            float2 f = __half22float2(h);
            acc[2 * j] += f.x;
            acc[2 * j + 1] += f.y;
        }
    }
    float4 r0, r1;
    r0.x = acc[0]; r0.y = acc[1]; r0.z = acc[2]; r0.w = acc[3];
    r1.x = acc[4]; r1.y = acc[5]; r1.z = acc[6]; r1.w = acc[7];
    reinterpret_cast<float4*>(out)[2 * gid] = r0;
    reinterpret_cast<float4*>(out)[2 * gid + 1] = r1;
}

extern "C" void kernel_launch(void* const* d_in, const int* in_sizes, int n_in,
                              void* d_out, int out_size) {
    const float* x   = (const float*)d_in[0];
    const int*   w   = (const int*)d_in[1];
    const float* saz = (const float*)d_in[2];
    float* out = (float*)d_out;

    cudaFuncSetAttribute(gemm_kernel, cudaFuncAttributeMaxDynamicSharedMemorySize, SMEM_TOTAL);

    prepass_kernel<<<DQ_BLOCKS + CV_BLOCKS, 256>>>(x, w, saz);
    gemm_kernel<<<GRID_MT * GRID_NT * SPLITK, 256, SMEM_TOTAL>>>();
    reduce_kernel<<<(DIM_M * DIM_N / 8) / 256, 256>>>(out);
}